// round 1
// baseline (speedup 1.0000x reference)
#include <cuda_runtime.h>
#include <cuda_bf16.h>
#include <math.h>

// Problem constants (fixed by the reference)
#define B_DIM 128
#define S_DIM 512
#define K_DIM 137
#define D_DIM (2 * K_DIM)      // 274
#define NCONN (K_DIM - 1)      // 136
#define WARPS_PER_BLOCK 8
#define THREADS (WARPS_PER_BLOCK * 32)
#define N_ITEMS (B_DIM * S_DIM)            // 65536
#define N_BLOCKS (N_ITEMS / WARPS_PER_BLOCK) // 8192

// Global accumulators (allocation-free scratch)
__device__ double g_pose_acc;
__device__ double g_bone_acc;

__global__ void t2p_init_kernel() {
    g_pose_acc = 0.0;
    g_bone_acc = 0.0;
}

// One warp handles one (b, s) item.
//   pred row:  predicted_poses[b, s, :]        (274 contiguous f32, read as float2)
//   tgt rows:  target_poses[b, 0, s, :] (t0), target_poses[b, 1, s, :] (t1)
//   pose uses t0[k+K], t1[k+K] == the s+1 rows (same contiguous stream).
// Items with s >= target_length[b] contribute nothing and skip all loads.
__global__ __launch_bounds__(THREADS) void t2p_main_kernel(
    const float* __restrict__ pred,
    const float* __restrict__ tgt,
    const int*   __restrict__ tlen)
{
    __shared__ float s_ex[WARPS_PER_BLOCK][K_DIM];
    __shared__ float s_ey[WARPS_PER_BLOCK][K_DIM];
    __shared__ float s_pose[WARPS_PER_BLOCK];
    __shared__ float s_bone[WARPS_PER_BLOCK];

    const int warp = threadIdx.x >> 5;
    const int lane = threadIdx.x & 31;
    const int item = blockIdx.x * WARPS_PER_BLOCK + warp;
    const int b = item >> 9;       // item / 512
    const int s = item & 511;      // item % 512

    float pose_sum = 0.0f;
    float bone_sum = 0.0f;

    const int L = tlen[b];
    const bool bone_valid = (s < L);
    const bool pose_valid = (s < L - 1) && (s < S_DIM - 1);  // pose_valid => bone_valid

    if (bone_valid) {
        const float2* __restrict__ p2 =
            (const float2*)(pred + (size_t)item * D_DIM);
        const float* __restrict__ t0 =
            tgt + ((size_t)(2 * b) * S_DIM + s) * K_DIM;       // c=0 (x) row at s
        const float* __restrict__ t1 =
            tgt + ((size_t)(2 * b + 1) * S_DIM + s) * K_DIM;   // c=1 (y) row at s

        float* ex = s_ex[warp];
        float* ey = s_ey[warp];

        for (int k = lane; k < K_DIM; k += 32) {
            float2 p = p2[k];                    // (pred_x[k], pred_y[k])
            ex[k] = p.x - t0[k];
            ey[k] = p.y - t1[k];
            if (pose_valid) {
                // next timestep rows: contiguous at +K
                pose_sum += fabsf(p.x - t0[k + K_DIM]) + fabsf(p.y - t1[k + K_DIM]);
            }
        }
        __syncwarp();

        for (int k = lane; k < NCONN; k += 32) {
            float dx = ex[k + 1] - ex[k];
            float dy = ey[k + 1] - ey[k];
            bone_sum = fmaf(dx, dx, bone_sum);
            bone_sum = fmaf(dy, dy, bone_sum);
        }
    }

    // Warp reduce
    #pragma unroll
    for (int o = 16; o > 0; o >>= 1) {
        pose_sum += __shfl_xor_sync(0xffffffffu, pose_sum, o);
        bone_sum += __shfl_xor_sync(0xffffffffu, bone_sum, o);
    }
    if (lane == 0) {
        s_pose[warp] = pose_sum;
        s_bone[warp] = bone_sum;
    }
    __syncthreads();

    // One double atomic per block per accumulator
    if (threadIdx.x == 0) {
        float ps = 0.0f, bs = 0.0f;
        #pragma unroll
        for (int w = 0; w < WARPS_PER_BLOCK; w++) {
            ps += s_pose[w];
            bs += s_bone[w];
        }
        atomicAdd(&g_pose_acc, (double)ps);
        atomicAdd(&g_bone_acc, (double)bs);
    }
}

__global__ void t2p_finalize_kernel(const int* __restrict__ tlen,
                                    float* __restrict__ out)
{
    const int lane = threadIdx.x;
    int lsum = 0;
    for (int b = lane; b < B_DIM; b += 32) lsum += tlen[b];
    #pragma unroll
    for (int o = 16; o > 0; o >>= 1)
        lsum += __shfl_xor_sync(0xffffffffu, lsum, o);

    if (lane == 0) {
        // mask_sum = sum(len);  pose_mask_sum = sum(min(len-1, S-1)) = sum(len-1)
        double mask_sum = (double)lsum;
        double pose_den = (double)(lsum - B_DIM);

        double pose_loss = g_pose_acc / (double)D_DIM / pose_den;
        double bone_loss = g_bone_acc * 0.5 / ((double)NCONN + 1e-8) / mask_sum;
        double total     = pose_loss + 0.1 * bone_loss;

        out[0] = (float)total;
        out[1] = (float)pose_loss;
        out[2] = (float)bone_loss;
    }
}

extern "C" void kernel_launch(void* const* d_in, const int* in_sizes, int n_in,
                              void* d_out, int out_size) {
    const float* pred = (const float*)d_in[0];   // [128, 512, 274] f32
    const float* tgt  = (const float*)d_in[1];   // [128, 2, 512, 137] f32
    const int*   tlen = (const int*)d_in[2];     // [128] i32
    float* out = (float*)d_out;                  // [3] f32: total, pose, bone

    t2p_init_kernel<<<1, 1>>>();
    t2p_main_kernel<<<N_BLOCKS, THREADS>>>(pred, tgt, tlen);
    t2p_finalize_kernel<<<1, 32>>>(tlen, out);
}